// round 9
// baseline (speedup 1.0000x reference)
#include <cuda_runtime.h>
#include <math.h>
#include <stdint.h>

#define NEXP     8
#define HDIM     4096
#define THREADS  512
#define BLOCKS   152
#define NTOK     16384
#define TBTOK    16                       // tokens per token-block
#define NTB      (NTOK / TBTOK)           // 1024
#define KCH      512                      // floats per k-chunk
#define NKC      (HDIM / KCH)             // 8 stages per token-block
#define NSLOT    3
#define STAGE_F  (TBTOK * KCH)            // 8192 floats per stage
#define STAGE_B  (STAGE_F * 4)            // 32768 bytes
#define ROW_B    (KCH * 4)                // 2048 bytes per token row

// shared layout (float offsets)
#define SW_OFF    0                       // weights: 32768 floats (128 KB)
#define STG_OFF   (NEXP * HDIM)           // stages:  3*8192 floats (96 KB)
#define RED_OFF   (STG_OFF + NSLOT * STAGE_F)  // red: 512 floats (2 KB)
#define MBAR_BOFF ((RED_OFF + 512) * 4)   // byte offset of barriers
#define SMEM_B    (MBAR_BOFF + 64)

// ---- mbarrier / bulk-async primitives ----
__device__ __forceinline__ void mbar_init(uint32_t a, uint32_t cnt) {
    asm volatile("mbarrier.init.shared.b64 [%0], %1;" :: "r"(a), "r"(cnt) : "memory");
}
__device__ __forceinline__ void mbar_expect_tx(uint32_t a, uint32_t bytes) {
    asm volatile("mbarrier.arrive.expect_tx.shared.b64 _, [%0], %1;"
                 :: "r"(a), "r"(bytes) : "memory");
}
__device__ __forceinline__ void mbar_arrive(uint32_t a) {
    asm volatile("mbarrier.arrive.shared.b64 _, [%0];" :: "r"(a) : "memory");
}
__device__ __forceinline__ void mbar_wait(uint32_t a, uint32_t parity) {
    asm volatile(
        "{\n\t.reg .pred P;\n\t"
        "W_%=:\n\t"
        "mbarrier.try_wait.parity.acquire.cta.shared::cta.b64 P, [%0], %1, 0x989680;\n\t"
        "@!P bra W_%=;\n\t"
        "}" :: "r"(a), "r"(parity) : "memory");
}
__device__ __forceinline__ void bulk_g2s(uint32_t dst, const void* src,
                                         uint32_t bytes, uint32_t mbar) {
    asm volatile(
        "cp.async.bulk.shared::cluster.global.mbarrier::complete_tx::bytes "
        "[%0], [%1], %2, [%3];"
        :: "r"(dst), "l"(src), "r"(bytes), "r"(mbar) : "memory");
}

__global__ __launch_bounds__(THREADS, 1)
void moe_router_kernel(const float* __restrict__ hs,
                       const float* __restrict__ rw,
                       float* __restrict__ out)
{
    extern __shared__ float sm[];
    const uint32_t smb = (uint32_t)__cvta_generic_to_shared(sm);
    const uint32_t mb_full  = smb + MBAR_BOFF;        // 3 x 8B
    const uint32_t mb_empty = smb + MBAR_BOFF + 24;   // 3 x 8B

    // Stage router weights into smem (once per block)
    float4* sw4 = reinterpret_cast<float4*>(sm);
    {
        const float4* rw4 = reinterpret_cast<const float4*>(rw);
        for (int i = threadIdx.x; i < NEXP * HDIM / 4; i += THREADS)
            sw4[i] = rw4[i];
    }
    if (threadIdx.x == 0) {
        #pragma unroll
        for (int k = 0; k < NSLOT; k++) {
            mbar_init(mb_full  + k * 8, 1);    // tx-based completion
            mbar_init(mb_empty + k * 8, 16);   // one arrive per warp
        }
    }
    __syncthreads();

    const int tid  = threadIdx.x;
    const int lane = tid & 31;
    const int wid  = tid >> 5;
    const int q    = wid >> 2;            // token quad 0..3
    const int s    = wid & 3;             // k-split 0..3

    const int ntb_local = (NTB - blockIdx.x + BLOCKS - 1) / BLOCKS;
    const int totalS    = ntb_local * NKC;

    // ---- producer: issue stage Sg (CTA-local index) ----
    auto issue = [&](int Sg) {
        if (Sg >= totalS) return;
        const int slot = Sg % NSLOT;
        if (Sg >= NSLOT) {
            const int w = Sg - NSLOT;                 // w-th empty wait
            mbar_wait(mb_empty + slot * 8, (w / NSLOT) & 1);
        }
        const int tb = blockIdx.x + (Sg / NKC) * BLOCKS;
        const int kc = Sg % NKC;
        const uint32_t fullb = mb_full + slot * 8;
        mbar_expect_tx(fullb, STAGE_B);
        const float* src = hs + (size_t)tb * TBTOK * HDIM + (size_t)kc * KCH;
        const uint32_t dst = smb + (STG_OFF + slot * STAGE_F) * 4;
        #pragma unroll
        for (int r = 0; r < TBTOK; r++)
            bulk_g2s(dst + r * ROW_B, src + (size_t)r * HDIM, ROW_B, fullb);
    };

    if (tid == 0) { issue(0); issue(1); issue(2); }

    float* out_w = out;
    float* out_i = out + (size_t)NTOK * 2;
    float* out_l = out + (size_t)NTOK * 4;

    int Sg = 0;
    for (int tbi = 0; tbi < ntb_local; tbi++) {
        const int tb = blockIdx.x + tbi * BLOCKS;

        float v[32];                       // v[t*8+e] partials for this warp's k-slices
        #pragma unroll
        for (int x = 0; x < 32; x++) v[x] = 0.0f;

        #pragma unroll 1
        for (int kc = 0; kc < NKC; kc++, Sg++) {
            const int slot = Sg % NSLOT;
            mbar_wait(mb_full + slot * 8, (Sg / NSLOT) & 1);

            const float4* st4 =
                reinterpret_cast<const float4*>(sm + STG_OFF + slot * STAGE_F);

            const int wbase = kc * 128 + s * 32 + lane;   // float4 idx in weight row
            float4 w[NEXP];
            #pragma unroll
            for (int e = 0; e < NEXP; e++)
                w[e] = sw4[e * (HDIM / 4) + wbase];

            #pragma unroll
            for (int tt = 0; tt < 4; tt++) {
                const float4 h = st4[(q * 4 + tt) * (KCH / 4) + s * 32 + lane];
                #pragma unroll
                for (int e = 0; e < NEXP; e++) {
                    v[tt * 8 + e] = fmaf(h.x, w[e].x, v[tt * 8 + e]);
                    v[tt * 8 + e] = fmaf(h.y, w[e].y, v[tt * 8 + e]);
                    v[tt * 8 + e] = fmaf(h.z, w[e].z, v[tt * 8 + e]);
                    v[tt * 8 + e] = fmaf(h.w, w[e].w, v[tt * 8 + e]);
                }
            }

            if (lane == 0) mbar_arrive(mb_empty + slot * 8);
            if (tid == 0) issue(Sg + NSLOT);
        }

        // Tree-exchange: lane L ends with this warp's full k-slice sum for
        // (token q*4 + (L>>3), expert L&7)
        #pragma unroll
        for (int o = 16; o >= 1; o >>= 1) {
            const bool up = (lane & o) != 0;
            #pragma unroll
            for (int j = 0; j < o; j++) {
                const float give = up ? v[j] : v[j + o];
                const float keep = up ? v[j + o] : v[j];
                const float recv = __shfl_xor_sync(0xffffffffu, give, o);
                v[j] = keep + recv;
            }
        }

        // Cross-s reduction via smem: red[(q*32+lane)*4 + s]
        sm[RED_OFF + (q * 32 + lane) * 4 + s] = v[0];
        __syncthreads();

        if (s == 0) {
            const float* rr = sm + RED_OFF + (q * 32 + lane) * 4;
            const float logit = (rr[0] + rr[1]) + (rr[2] + rr[3]);
            const size_t t0 = (size_t)tb * TBTOK + q * 4;
            const int sub = lane & 7;

            out_l[t0 * NEXP + lane] = logit;       // coalesced 128B per warp

            // Top-1 within each 8-lane token group (ties -> lowest index)
            float bv = logit; int bi = sub;
            #pragma unroll
            for (int o = 4; o >= 1; o >>= 1) {
                const float ov = __shfl_xor_sync(0xffffffffu, bv, o);
                const int   oi = __shfl_xor_sync(0xffffffffu, bi, o);
                if (ov > bv || (ov == bv && oi < bi)) { bv = ov; bi = oi; }
            }
            float sv = (sub == bi) ? -INFINITY : logit; int si = sub;
            #pragma unroll
            for (int o = 4; o >= 1; o >>= 1) {
                const float ov = __shfl_xor_sync(0xffffffffu, sv, o);
                const int   oi = __shfl_xor_sync(0xffffffffu, si, o);
                if (ov > sv || (ov == sv && oi < si)) { sv = ov; si = oi; }
            }

            if (sub == 0) {
                const size_t tok = t0 + (lane >> 3);
                const float e2 = __expf(sv - bv);
                const float r  = 1.0f / (1.0f + e2);
                out_w[tok * 2 + 0] = r;
                out_w[tok * 2 + 1] = e2 * r;
                out_i[tok * 2 + 0] = (float)bi;
                out_i[tok * 2 + 1] = (float)si;
            }
        }
        __syncthreads();   // protect red[] before next token-block overwrites
    }
}

extern "C" void kernel_launch(void* const* d_in, const int* in_sizes, int n_in,
                              void* d_out, int out_size)
{
    const float* hs = (const float*)d_in[0];   // hidden_states [4,4096,4096] f32
    const float* rw = (const float*)d_in[1];   // router_weight [8,4096] f32
    float* out = (float*)d_out;

    (void)in_sizes; (void)n_in; (void)out_size;

    cudaFuncSetAttribute(moe_router_kernel,
                         cudaFuncAttributeMaxDynamicSharedMemorySize, SMEM_B);

    moe_router_kernel<<<BLOCKS, THREADS, SMEM_B>>>(hs, rw, out);
}

// round 10
// speedup vs baseline: 1.5395x; 1.5395x over previous
#include <cuda_runtime.h>
#include <math.h>
#include <stdint.h>

#define NEXP    8
#define HDIM    4096
#define TOK     4
#define WARPS   16
#define THREADS 512
#define NTOK    16384            // 4 * 4096 tokens
#define NGROUP  (NTOK / TOK)     // 4096 warp-groups
#define H4      (HDIM / 4)       // 1024 float4 per row
#define KITERS  (H4 / 32)        // 32 k-iterations per group

#define SW_BYTES (NEXP * HDIM * 4)            // 128 KB weights
#define SLOT_B   (TOK * 512)                  // 2 KB: 4 tokens x 512B per k-iter
#define WBUF_B   (2 * SLOT_B)                 // 4 KB per warp (double buffer)
#define SMEM_B   (SW_BYTES + WARPS * WBUF_B)  // 192 KB total

// ---- cp.async primitives (16B, L1-bypass) ----
#define CP_ASYNC16(dst, src) \
    asm volatile("cp.async.cg.shared.global [%0], [%1], 16;" \
                 :: "r"(dst), "l"(src) : "memory")
#define CP_COMMIT() asm volatile("cp.async.commit_group;" ::: "memory")
#define CP_WAIT1()  asm volatile("cp.async.wait_group 1;"  ::: "memory")

__global__ __launch_bounds__(THREADS, 1)
void moe_router_kernel(const float* __restrict__ hs,
                       const float* __restrict__ rw,
                       float* __restrict__ out)
{
    extern __shared__ float sm[];
    float4* sw4 = reinterpret_cast<float4*>(sm);

    // Stage router weights into smem (coalesced, once per block)
    {
        const float4* rw4 = reinterpret_cast<const float4*>(rw);
        #pragma unroll
        for (int i = threadIdx.x; i < NEXP * H4; i += THREADS)
            sw4[i] = rw4[i];
    }
    __syncthreads();

    const int lane = threadIdx.x & 31;
    const int wid  = threadIdx.x >> 5;

    // This warp's private hidden double-buffer
    const uint32_t smb = (uint32_t)__cvta_generic_to_shared(sm);
    const uint32_t hb  = smb + SW_BYTES + wid * WBUF_B;   // + slot*SLOT_B + t*512 + lane*16
    const float4*  hgen = reinterpret_cast<const float4*>(
        reinterpret_cast<const char*>(sm) + SW_BYTES + wid * WBUF_B);
    // hgen[slot*128 + t*32 + lane]

    const int gwarp = blockIdx.x * WARPS + wid;
    const int nwarp = gridDim.x * WARPS;

    float* out_w = out;                     // [NTOK, 2] top-k weights
    float* out_i = out + (size_t)NTOK * 2;  // [NTOK, 2] indices (as float)
    float* out_l = out + (size_t)NTOK * 4;  // [NTOK, 8] raw logits

    for (int g = gwarp; g < NGROUP; g += nwarp) {
        const size_t t0 = (size_t)g * TOK;
        const float* hsrow = hs + t0 * HDIM;

        float v[TOK * NEXP];
        #pragma unroll
        for (int x = 0; x < TOK * NEXP; x++) v[x] = 0.0f;

        // Prologue: async-fill slots 0 (iter 0) and 1 (iter 1)
        #pragma unroll
        for (int s = 0; s < 2; s++) {
            #pragma unroll
            for (int t = 0; t < TOK; t++)
                CP_ASYNC16(hb + s * SLOT_B + t * 512 + lane * 16,
                           hsrow + (size_t)t * HDIM + (s * 32 + lane) * 4);
            CP_COMMIT();
        }

        #pragma unroll 4
        for (int i = 0; i < KITERS; i++) {
            CP_WAIT1();                      // iter i's group complete
            const int slot = i & 1;

            const int kk = i * 32 + lane;
            float4 w[NEXP];
            #pragma unroll
            for (int e = 0; e < NEXP; e++)
                w[e] = sw4[e * H4 + kk];

            float4 h[TOK];
            #pragma unroll
            for (int t = 0; t < TOK; t++)
                h[t] = hgen[slot * 128 + t * 32 + lane];

            // Refill this slot for iter i+2 (issued before FMA bulk;
            // DRAM return is ~600+ cyc, far after the LDS above complete)
            if (i + 2 < KITERS) {
                const int kf = (i + 2) * 32 + lane;
                #pragma unroll
                for (int t = 0; t < TOK; t++)
                    CP_ASYNC16(hb + slot * SLOT_B + t * 512 + lane * 16,
                               hsrow + (size_t)t * HDIM + kf * 4);
            }
            CP_COMMIT();                     // always: keeps group counting exact

            #pragma unroll
            for (int t = 0; t < TOK; t++) {
                #pragma unroll
                for (int e = 0; e < NEXP; e++) {
                    v[t * NEXP + e] = fmaf(h[t].x, w[e].x, v[t * NEXP + e]);
                    v[t * NEXP + e] = fmaf(h[t].y, w[e].y, v[t * NEXP + e]);
                    v[t * NEXP + e] = fmaf(h[t].z, w[e].z, v[t * NEXP + e]);
                    v[t * NEXP + e] = fmaf(h[t].w, w[e].w, v[t * NEXP + e]);
                }
            }
        }

        // Tree-exchange reduction: 31 SHFL; lane L ends with value index L=t*8+e
        #pragma unroll
        for (int o = 16; o >= 1; o >>= 1) {
            const bool up = (lane & o) != 0;
            #pragma unroll
            for (int j = 0; j < o; j++) {
                const float give = up ? v[j] : v[j + o];
                const float keep = up ? v[j + o] : v[j];
                const float recv = __shfl_xor_sync(0xffffffffu, give, o);
                v[j] = keep + recv;
            }
        }

        const float logit = v[0];       // logit[token = lane>>3][expert = lane&7]
        const int   sub   = lane & 7;

        // Coalesced logit store: 32 consecutive floats per warp
        out_l[t0 * NEXP + lane] = logit;

        // Top-1 within each 8-lane token group (ties -> lowest expert index)
        float bv = logit; int bi = sub;
        #pragma unroll
        for (int o = 4; o >= 1; o >>= 1) {
            const float ov = __shfl_xor_sync(0xffffffffu, bv, o);
            const int   oi = __shfl_xor_sync(0xffffffffu, bi, o);
            if (ov > bv || (ov == bv && oi < bi)) { bv = ov; bi = oi; }
        }
        // Top-2: exclude the winner, reduce again
        float sv = (sub == bi) ? -INFINITY : logit; int si = sub;
        #pragma unroll
        for (int o = 4; o >= 1; o >>= 1) {
            const float ov = __shfl_xor_sync(0xffffffffu, sv, o);
            const int   oi = __shfl_xor_sync(0xffffffffu, si, o);
            if (ov > sv || (ov == sv && oi < si)) { sv = ov; si = oi; }
        }

        if (sub == 0) {
            const size_t tok = t0 + (lane >> 3);
            // renormalized top-2 softmax weights
            const float e2 = __expf(sv - bv);
            const float r  = 1.0f / (1.0f + e2);
            out_w[tok * 2 + 0] = r;
            out_w[tok * 2 + 1] = e2 * r;
            out_i[tok * 2 + 0] = (float)bi;
            out_i[tok * 2 + 1] = (float)si;
        }
    }
}

extern "C" void kernel_launch(void* const* d_in, const int* in_sizes, int n_in,
                              void* d_out, int out_size)
{
    const float* hs = (const float*)d_in[0];   // hidden_states [4,4096,4096] f32
    const float* rw = (const float*)d_in[1];   // router_weight [8,4096] f32
    float* out = (float*)d_out;

    (void)in_sizes; (void)n_in; (void)out_size;

    cudaFuncSetAttribute(moe_router_kernel,
                         cudaFuncAttributeMaxDynamicSharedMemorySize, SMEM_B);

    moe_router_kernel<<<152, THREADS, SMEM_B>>>(hs, rw, out);
}

// round 11
// speedup vs baseline: 1.5554x; 1.0103x over previous
#include <cuda_runtime.h>
#include <math.h>
#include <stdint.h>

#define NEXP    8
#define HDIM    4096
#define TOK     4
#define WARPS   16
#define THREADS 512
#define NTOK    16384            // 4 * 4096 tokens
#define NGROUP  (NTOK / TOK)     // 4096 warp-groups
#define H4      (HDIM / 4)       // 1024 float4 per row
#define KITERS  (H4 / 32)        // 32 k-iterations per group
#define NSLOT   3

#define SW_BYTES (NEXP * HDIM * 4)                // 128 KB weights
#define SLOT_B   (TOK * 512)                      // 2 KB: 4 tokens x 512B
#define WBUF_B   (NSLOT * SLOT_B)                 // 6 KB per warp (3 slots)
#define SMEM_B   (SW_BYTES + WARPS * WBUF_B)      // 224 KB total

// ---- cp.async primitives (16B, L1-bypass) ----
#define CP_ASYNC16(dst, src) \
    asm volatile("cp.async.cg.shared.global [%0], [%1], 16;" \
                 :: "r"(dst), "l"(src) : "memory")
#define CP_COMMIT() asm volatile("cp.async.commit_group;" ::: "memory")
#define CP_WAIT2()  asm volatile("cp.async.wait_group 2;"  ::: "memory")

__global__ __launch_bounds__(THREADS, 1)
void moe_router_kernel(const float* __restrict__ hs,
                       const float* __restrict__ rw,
                       float* __restrict__ out)
{
    extern __shared__ float sm[];
    float4* sw4 = reinterpret_cast<float4*>(sm);

    // Stage router weights into smem (coalesced, once per block)
    {
        const float4* rw4 = reinterpret_cast<const float4*>(rw);
        #pragma unroll
        for (int i = threadIdx.x; i < NEXP * H4; i += THREADS)
            sw4[i] = rw4[i];
    }
    __syncthreads();

    const int lane = threadIdx.x & 31;
    const int wid  = threadIdx.x >> 5;

    // This warp's private 3-slot hidden ring buffer
    const uint32_t smb = (uint32_t)__cvta_generic_to_shared(sm);
    const uint32_t hb  = smb + SW_BYTES + wid * WBUF_B;   // + slotoff + t*512 + lane*16
    const float4*  hgen = reinterpret_cast<const float4*>(
        reinterpret_cast<const char*>(sm) + SW_BYTES + wid * WBUF_B);
    // hgen[slotoff/16 + t*32 + lane]

    const int gwarp = blockIdx.x * WARPS + wid;
    const int nwarp = gridDim.x * WARPS;

    float* out_w = out;                     // [NTOK, 2] top-k weights
    float* out_i = out + (size_t)NTOK * 2;  // [NTOK, 2] indices (as float)
    float* out_l = out + (size_t)NTOK * 4;  // [NTOK, 8] raw logits

    for (int g = gwarp; g < NGROUP; g += nwarp) {
        const size_t t0 = (size_t)g * TOK;
        const float* hsrow = hs + t0 * HDIM;

        float v[TOK * NEXP];
        #pragma unroll
        for (int x = 0; x < TOK * NEXP; x++) v[x] = 0.0f;

        // Prologue: async-fill slots 0,1,2 (iters 0,1,2), one group each
        #pragma unroll
        for (int s = 0; s < NSLOT; s++) {
            #pragma unroll
            for (int t = 0; t < TOK; t++)
                CP_ASYNC16(hb + s * SLOT_B + t * 512 + lane * 16,
                           hsrow + (size_t)t * HDIM + (s * 32 + lane) * 4);
            CP_COMMIT();
        }

        uint32_t slotoff = 0;                  // rotating byte offset 0,2K,4K
        #pragma unroll 1
        for (int i = 0; i < KITERS; i++) {
            CP_WAIT2();                        // iter i's group complete

            const int kk = i * 32 + lane;
            float4 w[NEXP];
            #pragma unroll
            for (int e = 0; e < NEXP; e++)
                w[e] = sw4[e * H4 + kk];

            float4 h[TOK];
            #pragma unroll
            for (int t = 0; t < TOK; t++)
                h[t] = hgen[(slotoff >> 4) + t * 32 + lane];

            // Refill this slot for iter i+NSLOT (prefetch distance 3)
            if (i + NSLOT < KITERS) {
                const int kf = (i + NSLOT) * 32 + lane;
                #pragma unroll
                for (int t = 0; t < TOK; t++)
                    CP_ASYNC16(hb + slotoff + t * 512 + lane * 16,
                               hsrow + (size_t)t * HDIM + kf * 4);
            }
            CP_COMMIT();                       // always: exact group counting

            #pragma unroll
            for (int t = 0; t < TOK; t++) {
                #pragma unroll
                for (int e = 0; e < NEXP; e++) {
                    v[t * NEXP + e] = fmaf(h[t].x, w[e].x, v[t * NEXP + e]);
                    v[t * NEXP + e] = fmaf(h[t].y, w[e].y, v[t * NEXP + e]);
                    v[t * NEXP + e] = fmaf(h[t].z, w[e].z, v[t * NEXP + e]);
                    v[t * NEXP + e] = fmaf(h[t].w, w[e].w, v[t * NEXP + e]);
                }
            }

            slotoff = (slotoff == (NSLOT - 1) * SLOT_B) ? 0u : slotoff + SLOT_B;
        }

        // Tree-exchange reduction: 31 SHFL; lane L ends with value index L=t*8+e
        #pragma unroll
        for (int o = 16; o >= 1; o >>= 1) {
            const bool up = (lane & o) != 0;
            #pragma unroll
            for (int j = 0; j < o; j++) {
                const float give = up ? v[j] : v[j + o];
                const float keep = up ? v[j + o] : v[j];
                const float recv = __shfl_xor_sync(0xffffffffu, give, o);
                v[j] = keep + recv;
            }
        }

        const float logit = v[0];       // logit[token = lane>>3][expert = lane&7]
        const int   sub   = lane & 7;

        // Coalesced logit store: 32 consecutive floats per warp
        out_l[t0 * NEXP + lane] = logit;

        // Top-1 within each 8-lane token group (ties -> lowest expert index)
        float bv = logit; int bi = sub;
        #pragma unroll
        for (int o = 4; o >= 1; o >>= 1) {
            const float ov = __shfl_xor_sync(0xffffffffu, bv, o);
            const int   oi = __shfl_xor_sync(0xffffffffu, bi, o);
            if (ov > bv || (ov == bv && oi < bi)) { bv = ov; bi = oi; }
        }
        // Top-2: exclude the winner, reduce again
        float sv = (sub == bi) ? -INFINITY : logit; int si = sub;
        #pragma unroll
        for (int o = 4; o >= 1; o >>= 1) {
            const float ov = __shfl_xor_sync(0xffffffffu, sv, o);
            const int   oi = __shfl_xor_sync(0xffffffffu, si, o);
            if (ov > sv || (ov == sv && oi < si)) { sv = ov; si = oi; }
        }

        if (sub == 0) {
            const size_t tok = t0 + (lane >> 3);
            // renormalized top-2 softmax weights
            const float e2 = __expf(sv - bv);
            const float r  = 1.0f / (1.0f + e2);
            out_w[tok * 2 + 0] = r;
            out_w[tok * 2 + 1] = e2 * r;
            out_i[tok * 2 + 0] = (float)bi;
            out_i[tok * 2 + 1] = (float)si;
        }
    }
}

extern "C" void kernel_launch(void* const* d_in, const int* in_sizes, int n_in,
                              void* d_out, int out_size)
{
    const float* hs = (const float*)d_in[0];   // hidden_states [4,4096,4096] f32
    const float* rw = (const float*)d_in[1];   // router_weight [8,4096] f32
    float* out = (float*)d_out;

    (void)in_sizes; (void)n_in; (void)out_size;

    cudaFuncSetAttribute(moe_router_kernel,
                         cudaFuncAttributeMaxDynamicSharedMemorySize, SMEM_B);

    moe_router_kernel<<<152, THREADS, SMEM_B>>>(hs, rw, out);
}